// round 13
// baseline (speedup 1.0000x reference)
#include <cuda_runtime.h>
#include <math.h>

#define MEM_LEN 131072
#define IN_DIM  256
#define OUT_DIM 512
#define BETA    1.0f

#define DIST_BLOCKS  (MEM_LEN / 8)                 // 16384, 8 rows per block
#define MD_BLOCKS    (MEM_LEN * IN_DIM / 4096)     // 8192, 4096 floats per block
#define TOTAL_BLOCKS (1 + MD_BLOCKS + DIST_BLOCKS) // 24577 (bid 0 = encoder)

// Scratch: device globals (no allocation allowed). Statically initialized for
// the first call; the finalize block resets them for every subsequent graph
// replay (self-cleaning => deterministic).
__device__ __align__(16) float g_enc[OUT_DIM];
__device__ unsigned int g_min_bits = 0x7f800000u;  // +inf
__device__ unsigned int g_done     = 0;
__device__ unsigned int g_flag     = 0;

// ---------------------------------------------------------------------------
// Encoder, executed by block 0 (256 threads): normalize x, GEMV (256x512),
// log_softmax -> g_enc. 512 GEMV tasks (4 k-partitions x 128 float4
// col-groups); each thread does 2 tasks. Softmax: 2 columns per thread.
// ---------------------------------------------------------------------------
__device__ void enc_block(const float* __restrict__ x,
                          const float* __restrict__ W,
                          const float* __restrict__ b,
                          const float* __restrict__ mean,
                          const float* __restrict__ stdv) {
    __shared__ float  s_new[IN_DIM];
    __shared__ float4 s_acc4[4][OUT_DIM / 4];   // [k-partition][col-group]
    __shared__ float  s_red[8];
    __shared__ float  s_bcast;

    int t = threadIdx.x;            // 0..255
    int lane = t & 31;
    int warp = t >> 5;              // 0..7

    {
        float s = stdv[t];
        s_new[t] = (s == 0.0f) ? 0.0f : (x[t] - mean[t]) / s;
    }
    __syncthreads();

    const float4* W4 = (const float4*)W;   // [256][128]
    #pragma unroll
    for (int task = 0; task < 2; task++) {
        int id = t + 256 * task;           // 0..511
        int cg = id & 127;                 // float4 column group
        int p  = id >> 7;                  // k-partition (64 k each)
        int k0 = p * 64;
        float4 acc = make_float4(0.f, 0.f, 0.f, 0.f);
        #pragma unroll 8
        for (int k = 0; k < 64; k++) {
            float  s = s_new[k0 + k];
            float4 w = __ldg(&W4[(size_t)(k0 + k) * 128 + cg]);
            acc.x = fmaf(s, w.x, acc.x);
            acc.y = fmaf(s, w.y, acc.y);
            acc.z = fmaf(s, w.z, acc.z);
            acc.w = fmaf(s, w.w, acc.w);
        }
        s_acc4[p][cg] = acc;
    }
    __syncthreads();

    // Thread t owns columns t and t+256.
    const float* s_acc = (const float*)s_acc4;   // [4][512]
    float l0 = b[t]       + s_acc[t]       + s_acc[512 + t]       + s_acc[1024 + t]       + s_acc[1536 + t];
    float l1 = b[t + 256] + s_acc[t + 256] + s_acc[512 + t + 256] + s_acc[1024 + t + 256] + s_acc[1536 + t + 256];

    // Block max over 512 logits
    float m = fmaxf(l0, l1);
    #pragma unroll
    for (int o = 16; o; o >>= 1) m = fmaxf(m, __shfl_xor_sync(0xffffffffu, m, o));
    if (lane == 0) s_red[warp] = m;
    __syncthreads();
    if (t < 32) {
        float v = (t < 8) ? s_red[t] : -INFINITY;
        #pragma unroll
        for (int o = 4; o; o >>= 1) v = fmaxf(v, __shfl_xor_sync(0xffffffffu, v, o));
        if (t == 0) s_bcast = v;
    }
    __syncthreads();
    float mx = s_bcast;

    // Block sum of exp
    float ssum = __expf(l0 - mx) + __expf(l1 - mx);
    #pragma unroll
    for (int o = 16; o; o >>= 1) ssum += __shfl_xor_sync(0xffffffffu, ssum, o);
    if (lane == 0) s_red[warp] = ssum;
    __syncthreads();
    if (t < 32) {
        float v = (t < 8) ? s_red[t] : 0.0f;
        #pragma unroll
        for (int o = 4; o; o >>= 1) v += __shfl_xor_sync(0xffffffffu, v, o);
        if (t == 0) s_bcast = v;
    }
    __syncthreads();
    float ls = logf(s_bcast);

    g_enc[t]       = l0 - mx - ls;
    g_enc[t + 256] = l1 - mx - ls;
    __threadfence();
    if (t == 0) atomicExch(&g_flag, 1u);   // publish
}

// ---------------------------------------------------------------------------
// k_all: ONE kernel.
//   bid 0                        : encoder (publishes g_enc via g_flag)
//   bid 1 .. MD_BLOCKS           : mem_data copy (independent of enc; these
//                                  fill the first ~7 waves and hide enc)
//   bid MD_BLOCKS+1 .. end       : L1-dist + memory copy (spin on g_flag,
//                                  which is set long before they schedule)
// Bulk reads use streaming hints (read-once); bulk stores use DEFAULT .wb so
// dirty lines keep full L2 residency for merge + batched writeback.
// ---------------------------------------------------------------------------
__global__ void __launch_bounds__(256) k_all(
        const float* __restrict__ mem,
        const float* __restrict__ md,
        const float* __restrict__ x,
        const float* __restrict__ W,
        const float* __restrict__ b,
        const float* __restrict__ mean,
        const float* __restrict__ stdv,
        const int*   __restrict__ count,
        float* __restrict__ out) {
    float* out_mem = out + 1;
    float* out_md  = out + 1 + (size_t)MEM_LEN * OUT_DIM;

    int bid = blockIdx.x;

    if (bid == 0) {
        enc_block(x, W, b, mean, stdv);
    } else if (bid <= MD_BLOCKS) {
        // ---- mem_data copy: contiguous 4096-float chunk, float4 loads ----
        size_t base4 = (size_t)(bid - 1) * 1024 + threadIdx.x;   // float4 units
        const float4* src4 = (const float4*)md;
        float4 v[4];
        #pragma unroll
        for (int j = 0; j < 4; j++)
            v[j] = __ldcs(&src4[base4 + 256 * j]);
        // Stores: scalar strided (output region is 4B-misaligned); each warp
        // STG.32 instruction writes 128 contiguous bytes. Default .wb caching.
        float* dst = out_md + (size_t)(bid - 1) * 4096;
        int t = threadIdx.x;
        #pragma unroll
        for (int j = 0; j < 4; j++) {
            int e = 4 * (t + 256 * j);      // element index of v[j].x
            dst[e]     = v[j].x;
            dst[e + 1] = v[j].y;
            dst[e + 2] = v[j].z;
            dst[e + 3] = v[j].w;
        }
    } else {
        // ---- L1 distance + copy, 8 rows (one per warp) ----
        __shared__ float s_enc[OUT_DIM];
        __shared__ float s_d[8];

        int lane = threadIdx.x & 31;
        int warp = threadIdx.x >> 5;
        int row  = (bid - 1 - MD_BLOCKS) * 8 + warp;

        // Wait for encoder (normally already done many waves ago).
        if (threadIdx.x == 0) {
            while (atomicAdd(&g_flag, 0u) == 0u) { __nanosleep(128); }
        }
        __syncthreads();

        // Stage enc in shared (L2 hits; bypass L1 for acquire safety).
        s_enc[threadIdx.x]       = __ldcg(&g_enc[threadIdx.x]);
        s_enc[threadIdx.x + 256] = __ldcg(&g_enc[threadIdx.x + 256]);
        __syncthreads();

        const float* mrow = mem + (size_t)row * OUT_DIM;
        float*       orow = out_mem + (size_t)row * OUT_DIM;

        float m[16];
        #pragma unroll
        for (int i = 0; i < 16; i++)
            m[i] = __ldcs(&mrow[lane + 32 * i]);

        float d = 0.0f;
        #pragma unroll
        for (int i = 0; i < 16; i++)
            d += fabsf(m[i] - s_enc[lane + 32 * i]);

        #pragma unroll
        for (int i = 0; i < 16; i++)
            orow[lane + 32 * i] = m[i];     // default .wb stores

        #pragma unroll
        for (int o = 16; o; o >>= 1) d += __shfl_xor_sync(0xffffffffu, d, o);
        if (lane == 0) s_d[warp] = d;
        __syncthreads();
        if (threadIdx.x == 0) {
            float mn = s_d[0];
            #pragma unroll
            for (int i = 1; i < 8; i++) mn = fminf(mn, s_d[i]);
            atomicMin(&g_min_bits, __float_as_uint(mn));   // d >= 0: float order == uint order
        }
    }

    // ---- last-done-block finalize ----
    __shared__ int s_last;
    __syncthreads();
    if (threadIdx.x == 0) {
        __threadfence();
        unsigned int ticket = atomicAdd(&g_done, 1u);
        s_last = (ticket == (unsigned)(TOTAL_BLOCKS - 1));
    }
    __syncthreads();

    if (s_last) {
        float loss = __uint_as_float(atomicAdd(&g_min_bits, 0u));
        int t = threadIdx.x;
        if (t == 0) out[0] = loss;
        if (loss <= BETA) {
            int pos = count[0] % MEM_LEN;
            out_mem[(size_t)pos * OUT_DIM + t]       = __ldcg(&g_enc[t]);
            out_mem[(size_t)pos * OUT_DIM + t + 256] = __ldcg(&g_enc[t + 256]);
            out_md[(size_t)pos * IN_DIM + t]         = x[t];
        }
        // Reset globals for the next graph replay (deterministic self-clean).
        __syncthreads();
        if (t == 0) {
            g_min_bits = 0x7f800000u;
            g_done     = 0u;
            atomicExch(&g_flag, 0u);
            __threadfence();
        }
    }
}

// ---------------------------------------------------------------------------
extern "C" void kernel_launch(void* const* d_in, const int* in_sizes, int n_in,
                              void* d_out, int out_size) {
    const float* x    = (const float*)d_in[0];
    const float* W    = (const float*)d_in[1];
    const float* b    = (const float*)d_in[2];
    const float* mem  = (const float*)d_in[3];
    const float* md   = (const float*)d_in[4];
    const float* mean = (const float*)d_in[5];
    const float* stdv = (const float*)d_in[6];
    const int*   cnt  = (const int*)d_in[7];
    float* out = (float*)d_out;

    k_all<<<TOTAL_BLOCKS, 256>>>(mem, md, x, W, b, mean, stdv, cnt, out);
}

// round 14
// speedup vs baseline: 1.1549x; 1.1549x over previous
#include <cuda_runtime.h>
#include <math.h>

#define MEM_LEN 131072
#define IN_DIM  256
#define OUT_DIM 512
#define BETA    1.0f

#define DIST_BLOCKS  (MEM_LEN / 8)                 // 16384, 8 rows per block
#define MD_BLOCKS    (MEM_LEN * IN_DIM / 4096)     // 8192, 4096 floats per block
#define TOTAL_BLOCKS (1 + MD_BLOCKS + DIST_BLOCKS) // 24577 (bid 0 = encoder)

// Scratch: device globals (no allocation allowed). Statically initialized for
// the first call; the finalize block resets them for every subsequent graph
// replay (self-cleaning => deterministic).
__device__ __align__(16) float g_enc[OUT_DIM];
__device__ unsigned int g_min_bits = 0x7f800000u;  // +inf
__device__ unsigned int g_done     = 0;
__device__ unsigned int g_flag     = 0;

// ---------------------------------------------------------------------------
// Encoder, executed by block 0 (256 threads): normalize x, GEMV (256x512),
// log_softmax -> g_enc. 512 GEMV tasks (4 k-partitions x 128 float4
// col-groups); each thread does 2 tasks. Softmax: 2 columns per thread.
// ---------------------------------------------------------------------------
__device__ void enc_block(const float* __restrict__ x,
                          const float* __restrict__ W,
                          const float* __restrict__ b,
                          const float* __restrict__ mean,
                          const float* __restrict__ stdv) {
    __shared__ float  s_new[IN_DIM];
    __shared__ float4 s_acc4[4][OUT_DIM / 4];   // [k-partition][col-group]
    __shared__ float  s_red[8];
    __shared__ float  s_bcast;

    int t = threadIdx.x;            // 0..255
    int lane = t & 31;
    int warp = t >> 5;              // 0..7

    {
        float s = stdv[t];
        s_new[t] = (s == 0.0f) ? 0.0f : (x[t] - mean[t]) / s;
    }
    __syncthreads();

    const float4* W4 = (const float4*)W;   // [256][128]
    #pragma unroll
    for (int task = 0; task < 2; task++) {
        int id = t + 256 * task;           // 0..511
        int cg = id & 127;                 // float4 column group
        int p  = id >> 7;                  // k-partition (64 k each)
        int k0 = p * 64;
        float4 acc = make_float4(0.f, 0.f, 0.f, 0.f);
        #pragma unroll 8
        for (int k = 0; k < 64; k++) {
            float  s = s_new[k0 + k];
            float4 w = __ldg(&W4[(size_t)(k0 + k) * 128 + cg]);
            acc.x = fmaf(s, w.x, acc.x);
            acc.y = fmaf(s, w.y, acc.y);
            acc.z = fmaf(s, w.z, acc.z);
            acc.w = fmaf(s, w.w, acc.w);
        }
        s_acc4[p][cg] = acc;
    }
    __syncthreads();

    // Thread t owns columns t and t+256.
    const float* s_acc = (const float*)s_acc4;   // [4][512]
    float l0 = b[t]       + s_acc[t]       + s_acc[512 + t]       + s_acc[1024 + t]       + s_acc[1536 + t];
    float l1 = b[t + 256] + s_acc[t + 256] + s_acc[512 + t + 256] + s_acc[1024 + t + 256] + s_acc[1536 + t + 256];

    // Block max over 512 logits
    float m = fmaxf(l0, l1);
    #pragma unroll
    for (int o = 16; o; o >>= 1) m = fmaxf(m, __shfl_xor_sync(0xffffffffu, m, o));
    if (lane == 0) s_red[warp] = m;
    __syncthreads();
    if (t < 32) {
        float v = (t < 8) ? s_red[t] : -INFINITY;
        #pragma unroll
        for (int o = 4; o; o >>= 1) v = fmaxf(v, __shfl_xor_sync(0xffffffffu, v, o));
        if (t == 0) s_bcast = v;
    }
    __syncthreads();
    float mx = s_bcast;

    // Block sum of exp
    float ssum = __expf(l0 - mx) + __expf(l1 - mx);
    #pragma unroll
    for (int o = 16; o; o >>= 1) ssum += __shfl_xor_sync(0xffffffffu, ssum, o);
    if (lane == 0) s_red[warp] = ssum;
    __syncthreads();
    if (t < 32) {
        float v = (t < 8) ? s_red[t] : 0.0f;
        #pragma unroll
        for (int o = 4; o; o >>= 1) v += __shfl_xor_sync(0xffffffffu, v, o);
        if (t == 0) s_bcast = v;
    }
    __syncthreads();
    float ls = logf(s_bcast);

    g_enc[t]       = l0 - mx - ls;
    g_enc[t + 256] = l1 - mx - ls;
    __threadfence();
    if (t == 0) atomicExch(&g_flag, 1u);   // publish
}

// ---------------------------------------------------------------------------
// k_all: ONE kernel.
//   bid 0                        : encoder (publishes g_enc via g_flag)
//   bid 1 .. MD_BLOCKS           : mem_data copy (independent of enc; these
//                                  fill the first ~7 waves and hide enc)
//   bid MD_BLOCKS+1 .. end       : L1-dist + memory copy (spin on g_flag,
//                                  which is set long before they schedule)
// PROVEN config (R12 = 123.0us): __ldcs bulk reads, __stcs bulk stores.
// Evict-first stores keep the 384MB dirty stream draining eagerly instead of
// hogging L2 (R13 showed default .wb costs 26us / -15% DRAM BW).
// ---------------------------------------------------------------------------
__global__ void __launch_bounds__(256) k_all(
        const float* __restrict__ mem,
        const float* __restrict__ md,
        const float* __restrict__ x,
        const float* __restrict__ W,
        const float* __restrict__ b,
        const float* __restrict__ mean,
        const float* __restrict__ stdv,
        const int*   __restrict__ count,
        float* __restrict__ out) {
    float* out_mem = out + 1;
    float* out_md  = out + 1 + (size_t)MEM_LEN * OUT_DIM;

    int bid = blockIdx.x;

    if (bid == 0) {
        enc_block(x, W, b, mean, stdv);
    } else if (bid <= MD_BLOCKS) {
        // ---- mem_data copy: contiguous 4096-float chunk, float4 loads ----
        size_t base4 = (size_t)(bid - 1) * 1024 + threadIdx.x;   // float4 units
        const float4* src4 = (const float4*)md;
        float4 v[4];
        #pragma unroll
        for (int j = 0; j < 4; j++)
            v[j] = __ldcs(&src4[base4 + 256 * j]);
        // Stores: scalar strided (output region is 4B-misaligned); each warp
        // STG.32 instruction writes 128 contiguous bytes. Evict-first (.cs).
        float* dst = out_md + (size_t)(bid - 1) * 4096;
        int t = threadIdx.x;
        #pragma unroll
        for (int j = 0; j < 4; j++) {
            int e = 4 * (t + 256 * j);      // element index of v[j].x
            __stcs(&dst[e],     v[j].x);
            __stcs(&dst[e + 1], v[j].y);
            __stcs(&dst[e + 2], v[j].z);
            __stcs(&dst[e + 3], v[j].w);
        }
    } else {
        // ---- L1 distance + copy, 8 rows (one per warp) ----
        __shared__ float s_enc[OUT_DIM];
        __shared__ float s_d[8];

        int lane = threadIdx.x & 31;
        int warp = threadIdx.x >> 5;
        int row  = (bid - 1 - MD_BLOCKS) * 8 + warp;

        // Wait for encoder (normally already done many waves ago).
        if (threadIdx.x == 0) {
            while (atomicAdd(&g_flag, 0u) == 0u) { __nanosleep(128); }
        }
        __syncthreads();

        // Stage enc in shared (L2 hits; bypass L1 for acquire safety).
        s_enc[threadIdx.x]       = __ldcg(&g_enc[threadIdx.x]);
        s_enc[threadIdx.x + 256] = __ldcg(&g_enc[threadIdx.x + 256]);
        __syncthreads();

        const float* mrow = mem + (size_t)row * OUT_DIM;
        float*       orow = out_mem + (size_t)row * OUT_DIM;

        float m[16];
        #pragma unroll
        for (int i = 0; i < 16; i++)
            m[i] = __ldcs(&mrow[lane + 32 * i]);

        float d = 0.0f;
        #pragma unroll
        for (int i = 0; i < 16; i++)
            d += fabsf(m[i] - s_enc[lane + 32 * i]);

        #pragma unroll
        for (int i = 0; i < 16; i++)
            __stcs(&orow[lane + 32 * i], m[i]);

        #pragma unroll
        for (int o = 16; o; o >>= 1) d += __shfl_xor_sync(0xffffffffu, d, o);
        if (lane == 0) s_d[warp] = d;
        __syncthreads();
        if (threadIdx.x == 0) {
            float mn = s_d[0];
            #pragma unroll
            for (int i = 1; i < 8; i++) mn = fminf(mn, s_d[i]);
            atomicMin(&g_min_bits, __float_as_uint(mn));   // d >= 0: float order == uint order
        }
    }

    // ---- last-done-block finalize ----
    __shared__ int s_last;
    __syncthreads();
    if (threadIdx.x == 0) {
        __threadfence();
        unsigned int ticket = atomicAdd(&g_done, 1u);
        s_last = (ticket == (unsigned)(TOTAL_BLOCKS - 1));
    }
    __syncthreads();

    if (s_last) {
        float loss = __uint_as_float(atomicAdd(&g_min_bits, 0u));
        int t = threadIdx.x;
        if (t == 0) out[0] = loss;
        if (loss <= BETA) {
            int pos = count[0] % MEM_LEN;
            out_mem[(size_t)pos * OUT_DIM + t]       = __ldcg(&g_enc[t]);
            out_mem[(size_t)pos * OUT_DIM + t + 256] = __ldcg(&g_enc[t + 256]);
            out_md[(size_t)pos * IN_DIM + t]         = x[t];
        }
        // Reset globals for the next graph replay (deterministic self-clean).
        __syncthreads();
        if (t == 0) {
            g_min_bits = 0x7f800000u;
            g_done     = 0u;
            atomicExch(&g_flag, 0u);
            __threadfence();
        }
    }
}

// ---------------------------------------------------------------------------
extern "C" void kernel_launch(void* const* d_in, const int* in_sizes, int n_in,
                              void* d_out, int out_size) {
    const float* x    = (const float*)d_in[0];
    const float* W    = (const float*)d_in[1];
    const float* b    = (const float*)d_in[2];
    const float* mem  = (const float*)d_in[3];
    const float* md   = (const float*)d_in[4];
    const float* mean = (const float*)d_in[5];
    const float* stdv = (const float*)d_in[6];
    const int*   cnt  = (const int*)d_in[7];
    float* out = (float*)d_out;

    k_all<<<TOTAL_BLOCKS, 256>>>(mem, md, x, W, b, mean, stdv, cnt, out);
}

// round 15
// speedup vs baseline: 1.2104x; 1.0481x over previous
#include <cuda_runtime.h>
#include <math.h>

#define MEM_LEN 131072
#define IN_DIM  256
#define OUT_DIM 512
#define BETA    1.0f

#define DIST_BLOCKS  (MEM_LEN / 8)                 // 16384, 8 rows per block
#define MD_BLOCKS    (MEM_LEN * IN_DIM / 4096)     // 8192, 4096 floats per block
#define TOTAL_BLOCKS (1 + MD_BLOCKS + DIST_BLOCKS) // 24577 (bid 0 = encoder)

// Scratch: device globals (no allocation allowed). Statically initialized for
// the first call; the finalize block resets them for every subsequent graph
// replay (self-cleaning => deterministic).
__device__ __align__(16) float g_enc[OUT_DIM];
__device__ unsigned int g_min_bits = 0x7f800000u;  // +inf
__device__ unsigned int g_done     = 0;
__device__ unsigned int g_flag     = 0;

// ---------------------------------------------------------------------------
// Encoder, executed by block 0 (256 threads): normalize x, GEMV (256x512),
// log_softmax -> g_enc. 512 GEMV tasks (4 k-partitions x 128 float4
// col-groups); each thread does 2 tasks. Softmax: 2 columns per thread.
// ---------------------------------------------------------------------------
__device__ void enc_block(const float* __restrict__ x,
                          const float* __restrict__ W,
                          const float* __restrict__ b,
                          const float* __restrict__ mean,
                          const float* __restrict__ stdv) {
    __shared__ float  s_new[IN_DIM];
    __shared__ float4 s_acc4[4][OUT_DIM / 4];   // [k-partition][col-group]
    __shared__ float  s_red[8];
    __shared__ float  s_bcast;

    int t = threadIdx.x;            // 0..255
    int lane = t & 31;
    int warp = t >> 5;              // 0..7

    {
        float s = stdv[t];
        s_new[t] = (s == 0.0f) ? 0.0f : (x[t] - mean[t]) / s;
    }
    __syncthreads();

    const float4* W4 = (const float4*)W;   // [256][128]
    #pragma unroll
    for (int task = 0; task < 2; task++) {
        int id = t + 256 * task;           // 0..511
        int cg = id & 127;                 // float4 column group
        int p  = id >> 7;                  // k-partition (64 k each)
        int k0 = p * 64;
        float4 acc = make_float4(0.f, 0.f, 0.f, 0.f);
        #pragma unroll 8
        for (int k = 0; k < 64; k++) {
            float  s = s_new[k0 + k];
            float4 w = __ldg(&W4[(size_t)(k0 + k) * 128 + cg]);
            acc.x = fmaf(s, w.x, acc.x);
            acc.y = fmaf(s, w.y, acc.y);
            acc.z = fmaf(s, w.z, acc.z);
            acc.w = fmaf(s, w.w, acc.w);
        }
        s_acc4[p][cg] = acc;
    }
    __syncthreads();

    // Thread t owns columns t and t+256.
    const float* s_acc = (const float*)s_acc4;   // [4][512]
    float l0 = b[t]       + s_acc[t]       + s_acc[512 + t]       + s_acc[1024 + t]       + s_acc[1536 + t];
    float l1 = b[t + 256] + s_acc[t + 256] + s_acc[512 + t + 256] + s_acc[1024 + t + 256] + s_acc[1536 + t + 256];

    // Block max over 512 logits
    float m = fmaxf(l0, l1);
    #pragma unroll
    for (int o = 16; o; o >>= 1) m = fmaxf(m, __shfl_xor_sync(0xffffffffu, m, o));
    if (lane == 0) s_red[warp] = m;
    __syncthreads();
    if (t < 32) {
        float v = (t < 8) ? s_red[t] : -INFINITY;
        #pragma unroll
        for (int o = 4; o; o >>= 1) v = fmaxf(v, __shfl_xor_sync(0xffffffffu, v, o));
        if (t == 0) s_bcast = v;
    }
    __syncthreads();
    float mx = s_bcast;

    // Block sum of exp
    float ssum = __expf(l0 - mx) + __expf(l1 - mx);
    #pragma unroll
    for (int o = 16; o; o >>= 1) ssum += __shfl_xor_sync(0xffffffffu, ssum, o);
    if (lane == 0) s_red[warp] = ssum;
    __syncthreads();
    if (t < 32) {
        float v = (t < 8) ? s_red[t] : 0.0f;
        #pragma unroll
        for (int o = 4; o; o >>= 1) v += __shfl_xor_sync(0xffffffffu, v, o);
        if (t == 0) s_bcast = v;
    }
    __syncthreads();
    float ls = logf(s_bcast);

    g_enc[t]       = l0 - mx - ls;
    g_enc[t + 256] = l1 - mx - ls;
    __threadfence();
    if (t == 0) atomicExch(&g_flag, 1u);   // publish
}

// ---------------------------------------------------------------------------
// k_all: ONE kernel.
//   bid 0                        : encoder (publishes g_enc via g_flag)
//   bid 1 .. MD_BLOCKS           : mem_data copy (independent of enc; these
//                                  fill the first ~7 waves and hide enc)
//   bid MD_BLOCKS+1 .. end       : L1-dist + memory copy (spin on g_flag,
//                                  which is set long before they schedule)
// PROVEN config (R12 = 123.0us): __ldcs bulk reads, __stcs bulk stores, and
// EVERY bulk store instruction warp-contiguous (lane stride 4B). R14 showed
// blocked stores in the md path alone cost +6us; R13 showed .wb stores cost
// +26us. Do not change either property.
// ---------------------------------------------------------------------------
__global__ void __launch_bounds__(256) k_all(
        const float* __restrict__ mem,
        const float* __restrict__ md,
        const float* __restrict__ x,
        const float* __restrict__ W,
        const float* __restrict__ b,
        const float* __restrict__ mean,
        const float* __restrict__ stdv,
        const int*   __restrict__ count,
        float* __restrict__ out) {
    float* out_mem = out + 1;
    float* out_md  = out + 1 + (size_t)MEM_LEN * OUT_DIM;

    int bid = blockIdx.x;

    if (bid == 0) {
        enc_block(x, W, b, mean, stdv);
    } else if (bid <= MD_BLOCKS) {
        // ---- mem_data copy: contiguous 4096-float chunk ----
        // Strided mapping (t + 256*j): every LDG/STG instruction covers 128
        // contiguous bytes per warp even though the dst base is 4B-offset.
        size_t base = (size_t)(bid - 1) * 4096 + threadIdx.x;
        float v[16];
        #pragma unroll
        for (int j = 0; j < 16; j++)
            v[j] = __ldcs(&md[base + 256 * j]);
        #pragma unroll
        for (int j = 0; j < 16; j++)
            __stcs(&out_md[base + 256 * j], v[j]);
    } else {
        // ---- L1 distance + copy, 8 rows (one per warp) ----
        __shared__ float s_enc[OUT_DIM];
        __shared__ float s_d[8];

        int lane = threadIdx.x & 31;
        int warp = threadIdx.x >> 5;
        int row  = (bid - 1 - MD_BLOCKS) * 8 + warp;

        // Wait for encoder (normally already done many waves ago).
        if (threadIdx.x == 0) {
            while (atomicAdd(&g_flag, 0u) == 0u) { __nanosleep(128); }
        }
        __syncthreads();

        // Stage enc in shared (L2 hits; bypass L1 for acquire safety).
        s_enc[threadIdx.x]       = __ldcg(&g_enc[threadIdx.x]);
        s_enc[threadIdx.x + 256] = __ldcg(&g_enc[threadIdx.x + 256]);
        __syncthreads();

        const float* mrow = mem + (size_t)row * OUT_DIM;
        float*       orow = out_mem + (size_t)row * OUT_DIM;

        float m[16];
        #pragma unroll
        for (int i = 0; i < 16; i++)
            m[i] = __ldcs(&mrow[lane + 32 * i]);

        float d = 0.0f;
        #pragma unroll
        for (int i = 0; i < 16; i++)
            d += fabsf(m[i] - s_enc[lane + 32 * i]);

        #pragma unroll
        for (int i = 0; i < 16; i++)
            __stcs(&orow[lane + 32 * i], m[i]);

        #pragma unroll
        for (int o = 16; o; o >>= 1) d += __shfl_xor_sync(0xffffffffu, d, o);
        if (lane == 0) s_d[warp] = d;
        __syncthreads();
        if (threadIdx.x == 0) {
            float mn = s_d[0];
            #pragma unroll
            for (int i = 1; i < 8; i++) mn = fminf(mn, s_d[i]);
            atomicMin(&g_min_bits, __float_as_uint(mn));   // d >= 0: float order == uint order
        }
    }

    // ---- last-done-block finalize ----
    __shared__ int s_last;
    __syncthreads();
    if (threadIdx.x == 0) {
        __threadfence();
        unsigned int ticket = atomicAdd(&g_done, 1u);
        s_last = (ticket == (unsigned)(TOTAL_BLOCKS - 1));
    }
    __syncthreads();

    if (s_last) {
        float loss = __uint_as_float(atomicAdd(&g_min_bits, 0u));
        int t = threadIdx.x;
        if (t == 0) out[0] = loss;
        if (loss <= BETA) {
            int pos = count[0] % MEM_LEN;
            out_mem[(size_t)pos * OUT_DIM + t]       = __ldcg(&g_enc[t]);
            out_mem[(size_t)pos * OUT_DIM + t + 256] = __ldcg(&g_enc[t + 256]);
            out_md[(size_t)pos * IN_DIM + t]         = x[t];
        }
        // Reset globals for the next graph replay (deterministic self-clean).
        __syncthreads();
        if (t == 0) {
            g_min_bits = 0x7f800000u;
            g_done     = 0u;
            atomicExch(&g_flag, 0u);
            __threadfence();
        }
    }
}

// ---------------------------------------------------------------------------
extern "C" void kernel_launch(void* const* d_in, const int* in_sizes, int n_in,
                              void* d_out, int out_size) {
    const float* x    = (const float*)d_in[0];
    const float* W    = (const float*)d_in[1];
    const float* b    = (const float*)d_in[2];
    const float* mem  = (const float*)d_in[3];
    const float* md   = (const float*)d_in[4];
    const float* mean = (const float*)d_in[5];
    const float* stdv = (const float*)d_in[6];
    const int*   cnt  = (const int*)d_in[7];
    float* out = (float*)d_out;

    k_all<<<TOTAL_BLOCKS, 256>>>(mem, md, x, W, b, mean, stdv, cnt, out);
}